// round 1
// baseline (speedup 1.0000x reference)
#include <cuda_runtime.h>
#include <math.h>

#define BT 32
#define DIM 64
#define HW 4096
#define N2 131072
#define IMOFF 8388608
#define LNEPS 1e-5f

// ---------------- scratch (device globals; no allocations allowed) ----------------
__device__ __align__(16) float g_xc[(size_t)BT * HW * 128];   // 64 MB: LN'd conv input (pixel-major, 128 ch)
__device__ __align__(16) float g_x1r[(size_t)BT * DIM * HW];  // stage-1 output (real)
__device__ __align__(16) float g_x1i[(size_t)BT * DIM * HW];  // stage-1 output (imag)
__device__ float g_ar[BT * DIM], g_ai[BT * DIM], g_fr[BT * DIM], g_fi[BT * DIM], g_sq[BT];
__device__ __align__(16) float g_gates[4 * N2];
__device__ __align__(16) float g_hid[(size_t)512 * N2];       // 256 MB MoE intermediate [j][n2]

__device__ __forceinline__ float gelu_tanh(float x) {
    float t = 0.7978845608028654f * (x + 0.044715f * x * x * x);
    return 0.5f * x * (1.0f + tanhf(t));
}
__device__ __forceinline__ void fma4(float4& a, float s, float4 w) {
    a.x = fmaf(s, w.x, a.x); a.y = fmaf(s, w.y, a.y);
    a.z = fmaf(s, w.z, a.z); a.w = fmaf(s, w.w, a.w);
}

// ---------------- K0: per-(b,t,d) decay & forcing ----------------
__global__ void k_setup(const float* __restrict__ dt, const float* __restrict__ lam_re,
                        const float* __restrict__ lam_im) {
    int i = blockIdx.x * blockDim.x + threadIdx.x;
    if (i >= BT * DIM) return;
    int bt = i >> 6, d = i & 63;
    float dtv = dt[bt];
    float x = lam_re[d];
    float sp = (x > 20.f) ? x : log1pf(expf(x));
    float lr = -sp, li = lam_im[d];
    float er = expf(lr * dtv);
    float ar = er * cosf(li * dtv), ai = er * sinf(li * dtv);
    float den = lr * lr + li * li;
    g_ar[i] = ar; g_ai[i] = ai;
    g_fr[i] = ((ar - 1.f) * lr + ai * li) / den;
    g_fi[i] = (ai * lr - (ar - 1.f) * li) / den;
    if (d == 0) g_sq[bt] = 0.01f * sqrtf(dtv);
}

// ---------------- K1: spatial complex LayerNorm -> g_xc ----------------
// block = 64 pixels, shared transpose so both the strided gather and the
// channel-last write are coalesced.
__global__ void k_sln(const float* __restrict__ xr, const float* __restrict__ xi,
                      const float* __restrict__ w, const float* __restrict__ b) {
    __shared__ float sh[128][65];
    __shared__ float smu[64], srs[64];
    int t = threadIdx.x;
    int p0 = blockIdx.x * 64;
    int bt = p0 >> 12, hw0 = p0 & 4095;
    for (int r = 0; r < 32; r++) {
        int idx = t + 256 * r;
        int c = idx >> 6, p = idx & 63;
        float v = (c < 64) ? xr[((size_t)(bt * 64 + c)) * 4096 + hw0 + p]
                           : xi[((size_t)(bt * 64 + c - 64)) * 4096 + hw0 + p];
        sh[c][p] = v;
    }
    __syncthreads();
    int wid = t >> 5, lane = t & 31;
    if (wid < 8) {
        for (int pp = 0; pp < 8; pp++) {
            int p = wid * 8 + pp;
            float s = 0.f, s2 = 0.f;
            for (int cc = lane; cc < 128; cc += 32) {
                float v = sh[cc][p]; s += v; s2 += v * v;
            }
            for (int o = 16; o; o >>= 1) {
                s += __shfl_xor_sync(0xffffffffu, s, o);
                s2 += __shfl_xor_sync(0xffffffffu, s2, o);
            }
            if (lane == 0) {
                float mu = s * (1.f / 128.f);
                smu[p] = mu;
                srs[p] = rsqrtf(s2 * (1.f / 128.f) - mu * mu + LNEPS);
            }
        }
    }
    __syncthreads();
    for (int r = 0; r < 32; r++) {
        int idx = t + 256 * r;
        int p = idx >> 7, c = idx & 127;
        float v = (sh[c][p] - smu[p]) * srs[p] * w[c] + b[c];
        g_xc[((size_t)(p0 + p)) * 128 + c] = v;
    }
}

// ---------------- K2: 3x3 conv 128->128 + bias + residual -> x1 ----------------
// tile 8(h) x 16(w) pixels x 128 co per block; 9 taps x 4 ci-chunks of 32.
__global__ void k_conv(const float* __restrict__ cw, const float* __restrict__ cb,
                       const float* __restrict__ xr, const float* __restrict__ xi) {
    __shared__ float in_sh[32][129];
    __shared__ float4 w4[32][32];
    int t = threadIdx.x;
    int w0 = blockIdx.x * 16, h0 = blockIdx.y * 8, bt = blockIdx.z;
    int lane = t & 31, cg = t >> 5;   // cg: co-group of 16
    float4 acc[4][4];
    for (int k = 0; k < 4; k++) for (int q = 0; q < 4; q++) acc[k][q] = make_float4(0, 0, 0, 0);
    const float* img = g_xc + (size_t)bt * HW * 128;
    for (int ch = 0; ch < 4; ch++) {
        int ci0 = ch * 32;
        for (int tap = 0; tap < 9; tap++) {
            int dy = tap / 3 - 1, dx = tap % 3 - 1;
            __syncthreads();
            for (int r = 0; r < 4; r++) {
                int idx = t + 256 * r;
                int p = idx >> 3, c4 = idx & 7;
                int y = p >> 4, x = p & 15;
                int gh = h0 + y + dy, gw = w0 + x + dx;
                float4 v = make_float4(0, 0, 0, 0);
                if ((unsigned)gh < 64u && (unsigned)gw < 64u)
                    v = *(const float4*)(img + ((size_t)(gh * 64 + gw)) * 128 + ci0 + c4 * 4);
                in_sh[c4 * 4 + 0][p] = v.x; in_sh[c4 * 4 + 1][p] = v.y;
                in_sh[c4 * 4 + 2][p] = v.z; in_sh[c4 * 4 + 3][p] = v.w;
            }
            for (int r = 0; r < 4; r++) {
                int idx = t + 256 * r;
                int c = idx >> 5, j4 = idx & 31;
                w4[c][j4] = *(const float4*)(cw + ((size_t)(tap * 128 + ci0 + c)) * 128 + j4 * 4);
            }
            __syncthreads();
#pragma unroll 4
            for (int c = 0; c < 32; c++) {
                float iv0 = in_sh[c][lane], iv1 = in_sh[c][lane + 32];
                float iv2 = in_sh[c][lane + 64], iv3 = in_sh[c][lane + 96];
#pragma unroll
                for (int q = 0; q < 4; q++) {
                    float4 wv = w4[c][cg * 4 + q];
                    fma4(acc[0][q], iv0, wv);
                    fma4(acc[1][q], iv1, wv);
                    fma4(acc[2][q], iv2, wv);
                    fma4(acc[3][q], iv3, wv);
                }
            }
        }
    }
    for (int q = 0; q < 4; q++) {
        for (int m = 0; m < 4; m++) {
            int co = cg * 16 + q * 4 + m;
            float bias = cb[co];
            for (int k = 0; k < 4; k++) {
                int p = lane + 32 * k;
                int y = p >> 4, x = p & 15;
                float v = ((const float*)&acc[k][q])[m] + bias;
                if (co < 64) {
                    size_t gi = ((size_t)(bt * 64 + co)) * 4096 + (h0 + y) * 64 + (w0 + x);
                    g_x1r[gi] = v + xr[gi];
                } else {
                    size_t gi = ((size_t)(bt * 64 + co - 64)) * 4096 + (h0 + y) * 64 + (w0 + x);
                    g_x1i[gi] = v + xi[gi];
                }
            }
        }
    }
}

// ---------------- K3: temporal LN + encode + scan + decode -> d_out ----------------
// block = (b, h, 16 consecutive w); 1024 threads. Loops t sequentially (scan).
__global__ void k_temp(const float* __restrict__ ltw, const float* __restrict__ ltb,
                       const float* __restrict__ encr, const float* __restrict__ enci,
                       const float* __restrict__ decr, const float* __restrict__ deci,
                       const float* __restrict__ sbr, const float* __restrict__ sbi,
                       const float* __restrict__ nzr, const float* __restrict__ nzi,
                       float* __restrict__ out) {
    __shared__ float or_r[64][17], or_i[64][17], xn_r[64][17], xn_i[64][17];
    __shared__ float h_r[64][17], h_i[64][17], dr_sh[64][17];
    __shared__ float smu[16], srs[16];
    int t = threadIdx.x;
    int w0 = blockIdx.x * 16, h = blockIdx.y, b = blockIdx.z;
    int e = t & 63, w = t >> 6;        // encode/decode mapping
    int d_l = t >> 4, w_l = t & 15;    // load/write mapping
    int wid = t >> 5, lane = t & 31;
    float hr = 0.f, hi = 0.f;
    size_t nbase = ((size_t)(b * 4096 + h * 64 + w0 + w)) * 1024;  // noise (N,T,D)
    for (int tt = 0; tt < 16; tt++) {
        int btt = b * 16 + tt;
        size_t gbase = ((size_t)(btt * 64)) * 4096 + h * 64 + w0;
        or_r[d_l][w_l] = g_x1r[gbase + (size_t)d_l * 4096 + w_l];
        or_i[d_l][w_l] = g_x1i[gbase + (size_t)d_l * 4096 + w_l];
        __syncthreads();
        if (wid < 16) {
            float v0 = or_r[lane][wid], v1 = or_r[lane + 32][wid];
            float v2 = or_i[lane][wid], v3 = or_i[lane + 32][wid];
            float s = v0 + v1 + v2 + v3;
            float s2 = v0 * v0 + v1 * v1 + v2 * v2 + v3 * v3;
            for (int o = 16; o; o >>= 1) {
                s += __shfl_xor_sync(0xffffffffu, s, o);
                s2 += __shfl_xor_sync(0xffffffffu, s2, o);
            }
            if (lane == 0) {
                float mu = s * (1.f / 128.f);
                smu[wid] = mu;
                srs[wid] = rsqrtf(s2 * (1.f / 128.f) - mu * mu + LNEPS);
            }
        }
        __syncthreads();
        {
            float mu = smu[w_l], rs = srs[w_l];
            xn_r[d_l][w_l] = (or_r[d_l][w_l] - mu) * rs * ltw[d_l] + ltb[d_l];
            xn_i[d_l][w_l] = (or_i[d_l][w_l] - mu) * rs * ltw[64 + d_l] + ltb[64 + d_l];
        }
        __syncthreads();
        // encode: u_e = sum_d xn_d * Eb[d][e]
        float ur = 0.f, ui = 0.f;
#pragma unroll 8
        for (int dd = 0; dd < 64; dd++) {
            float xrv = xn_r[dd][w], xiv = xn_i[dd][w];
            float er = encr[dd * 64 + e], ei = enci[dd * 64 + e];
            ur = fmaf(xrv, er, ur); ur = fmaf(-xiv, ei, ur);
            ui = fmaf(xrv, ei, ui); ui = fmaf(xiv, er, ui);
        }
        ur += sbr[e]; ui += sbi[e];
        int ai_ = btt * 64 + e;
        float fr = g_fr[ai_], fi = g_fi[ai_], sq = g_sq[btt];
        float tur = ur * fr - ui * fi + sq * nzr[nbase + tt * 64 + e];
        float tui = ur * fi + ui * fr + sq * nzi[nbase + tt * 64 + e];
        float ar = g_ar[ai_], aiv = g_ai[ai_];
        float nhr = ar * hr - aiv * hi + tur;
        float nhi = ar * hi + aiv * hr + tui;
        hr = nhr; hi = nhi;
        h_r[e][w] = hr; h_i[e][w] = hi;
        __syncthreads();
        // decode: drift_d = Re(sum_e h_e * Db[e][d])  (thread's e acts as d)
        float dr = 0.f;
#pragma unroll 8
        for (int ee = 0; ee < 64; ee++) {
            dr = fmaf(h_r[ee][w], decr[ee * 64 + e], dr);
            dr = fmaf(-h_i[ee][w], deci[ee * 64 + e], dr);
        }
        dr_sh[e][w] = dr;
        __syncthreads();
        size_t gr = gbase + (size_t)d_l * 4096 + w_l;
        out[gr] = or_r[d_l][w_l] + dr_sh[d_l][w_l];
        out[IMOFF + gr] = or_i[d_l][w_l];
        __syncthreads();
    }
}

// ---------------- K4: router gates ----------------
__global__ void k_gates(const float* __restrict__ rw, const float* __restrict__ rb,
                        const float* __restrict__ out) {
    int n2 = blockIdx.x * 256 + threadIdx.x;
    int bt = n2 >> 12, hw = n2 & 4095;
    const float* pr = out + (size_t)bt * 64 * 4096 + hw;
    const float* pi = out + IMOFF + (size_t)bt * 64 * 4096 + hw;
    float l0 = rb[0], l1 = rb[1], l2 = rb[2], l3 = rb[3];
    for (int c = 0; c < 64; c++) {
        float v = pr[(size_t)c * 4096];
        float4 wv = *(const float4*)(rw + c * 4);
        l0 = fmaf(v, wv.x, l0); l1 = fmaf(v, wv.y, l1);
        l2 = fmaf(v, wv.z, l2); l3 = fmaf(v, wv.w, l3);
    }
    for (int c = 0; c < 64; c++) {
        float v = pi[(size_t)c * 4096];
        float4 wv = *(const float4*)(rw + (64 + c) * 4);
        l0 = fmaf(v, wv.x, l0); l1 = fmaf(v, wv.y, l1);
        l2 = fmaf(v, wv.z, l2); l3 = fmaf(v, wv.w, l3);
    }
    float m = fmaxf(fmaxf(l0, l1), fmaxf(l2, l3));
    float e0 = expf(l0 - m), e1 = expf(l1 - m), e2 = expf(l2 - m), e3 = expf(l3 - m);
    float inv = 1.f / (e0 + e1 + e2 + e3);
    g_gates[0 * N2 + n2] = e0 * inv;
    g_gates[1 * N2 + n2] = e1 * inv;
    g_gates[2 * N2 + n2] = e2 * inv;
    g_gates[3 * N2 + n2] = e3 * inv;
}

// ---------------- K5: MoE GEMM1: hid = gate * gelu(tok @ w1[e] + b1[e]) ----------------
// 64 tokens x 128 cols per block; tokens gathered straight from d_out.
__global__ void k_g1(const float* __restrict__ w1, const float* __restrict__ b1,
                     const float* __restrict__ out) {
    __shared__ float tok_sh[32][65];
    __shared__ float4 w4[32][32];
    int t = threadIdx.x;
    int t0 = blockIdx.x * 64;
    int e = blockIdx.y;
    int token = t & 63, cg = t >> 6;
    int bt = t0 >> 12, hw0 = t0 & 4095;
    float4 acc[8];
    for (int q = 0; q < 8; q++) acc[q] = make_float4(0, 0, 0, 0);
    for (int kc = 0; kc < 4; kc++) {
        int ci0 = kc * 32;
        __syncthreads();
        for (int r = 0; r < 8; r++) {
            int idx = t + 256 * r;
            int kk = idx >> 6, tl = idx & 63;
            int c = ci0 + kk;
            float v = (c < 64) ? out[((size_t)(bt * 64 + c)) * 4096 + hw0 + tl]
                               : out[IMOFF + ((size_t)(bt * 64 + c - 64)) * 4096 + hw0 + tl];
            tok_sh[kk][tl] = v;
        }
        for (int r = 0; r < 4; r++) {
            int idx = t + 256 * r;
            int kk = idx >> 5, j4 = idx & 31;
            w4[kk][j4] = *(const float4*)(w1 + (size_t)e * 16384 + (ci0 + kk) * 128 + j4 * 4);
        }
        __syncthreads();
#pragma unroll 4
        for (int kk = 0; kk < 32; kk++) {
            float tv = tok_sh[kk][token];
#pragma unroll
            for (int q = 0; q < 8; q++) fma4(acc[q], tv, w4[kk][cg * 8 + q]);
        }
    }
    float gate = g_gates[e * N2 + t0 + token];
    for (int q = 0; q < 8; q++) {
        for (int m = 0; m < 4; m++) {
            int j = cg * 32 + q * 4 + m;
            float v = ((const float*)&acc[q])[m] + b1[e * 128 + j];
            g_hid[((size_t)(e * 128 + j)) * N2 + t0 + token] = gelu_tanh(v) * gate;
        }
    }
}

// ---------------- K6: MoE GEMM2: d_out += hid @ w2cat + gated b2 ----------------
__global__ void k_g2(const float* __restrict__ w2, const float* __restrict__ b2,
                     float* __restrict__ out) {
    __shared__ float hs[32][65];
    __shared__ float4 w4[32][32];
    int t = threadIdx.x;
    int t0 = blockIdx.x * 64;
    int token = t & 63, cg = t >> 6;
    float4 acc[8];
    for (int q = 0; q < 8; q++) acc[q] = make_float4(0, 0, 0, 0);
    for (int kc = 0; kc < 16; kc++) {
        int k0 = kc * 32;
        __syncthreads();
        for (int r = 0; r < 8; r++) {
            int idx = t + 256 * r;
            int kk = idx >> 6, tl = idx & 63;
            hs[kk][tl] = g_hid[((size_t)(k0 + kk)) * N2 + t0 + tl];
        }
        for (int r = 0; r < 4; r++) {
            int idx = t + 256 * r;
            int kk = idx >> 5, j4 = idx & 31;
            int kg = k0 + kk;
            int e = kg >> 7, hh = kg & 127;
            w4[kk][j4] = *(const float4*)(w2 + (size_t)e * 16384 + hh * 128 + j4 * 4);
        }
        __syncthreads();
#pragma unroll 4
        for (int kk = 0; kk < 32; kk++) {
            float tv = hs[kk][token];
#pragma unroll
            for (int q = 0; q < 8; q++) fma4(acc[q], tv, w4[kk][cg * 8 + q]);
        }
    }
    int n2 = t0 + token;
    float g0 = g_gates[0 * N2 + n2], g1 = g_gates[1 * N2 + n2];
    float g2 = g_gates[2 * N2 + n2], g3 = g_gates[3 * N2 + n2];
    int bt = t0 >> 12;
    int hw = (t0 & 4095) + token;
    for (int q = 0; q < 8; q++) {
        for (int m = 0; m < 4; m++) {
            int o = cg * 32 + q * 4 + m;
            float bterm = g0 * b2[o] + g1 * b2[128 + o] + g2 * b2[256 + o] + g3 * b2[384 + o];
            float delta = ((const float*)&acc[q])[m] + bterm;
            size_t gi = (o < 64) ? ((size_t)(bt * 64 + o)) * 4096 + hw
                                 : IMOFF + ((size_t)(bt * 64 + o - 64)) * 4096 + hw;
            out[gi] += delta;
        }
    }
}

extern "C" void kernel_launch(void* const* d_in, const int* in_sizes, int n_in,
                              void* d_out, int out_size) {
    const float* x_real = (const float*)d_in[0];
    const float* x_imag = (const float*)d_in[1];
    const float* dt     = (const float*)d_in[2];
    const float* nz_r   = (const float*)d_in[3];
    const float* nz_i   = (const float*)d_in[4];
    const float* ln_s_w = (const float*)d_in[5];
    const float* ln_s_b = (const float*)d_in[6];
    const float* conv_w = (const float*)d_in[7];
    const float* conv_b = (const float*)d_in[8];
    const float* ln_t_w = (const float*)d_in[9];
    const float* ln_t_b = (const float*)d_in[10];
    const float* lam_re = (const float*)d_in[11];
    const float* lam_im = (const float*)d_in[12];
    const float* sb_re  = (const float*)d_in[13];
    const float* sb_im  = (const float*)d_in[14];
    const float* enc_re = (const float*)d_in[15];
    const float* enc_im = (const float*)d_in[16];
    const float* dec_re = (const float*)d_in[17];
    const float* dec_im = (const float*)d_in[18];
    const float* rw     = (const float*)d_in[19];
    const float* rb     = (const float*)d_in[20];
    const float* w1     = (const float*)d_in[21];
    const float* b1     = (const float*)d_in[22];
    const float* w2     = (const float*)d_in[23];
    const float* b2     = (const float*)d_in[24];
    float* out = (float*)d_out;

    k_setup<<<8, 256>>>(dt, lam_re, lam_im);
    k_sln<<<2048, 256>>>(x_real, x_imag, ln_s_w, ln_s_b);
    k_conv<<<dim3(4, 8, 32), 256>>>(conv_w, conv_b, x_real, x_imag);
    k_temp<<<dim3(4, 64, 2), 1024>>>(ln_t_w, ln_t_b, enc_re, enc_im, dec_re, dec_im,
                                     sb_re, sb_im, nz_r, nz_i, out);
    k_gates<<<512, 256>>>(rw, rb, out);
    k_g1<<<dim3(2048, 4), 256>>>(w1, b1, out);
    k_g2<<<2048, 256>>>(w2, b2, out);
}

// round 2
// speedup vs baseline: 1.1077x; 1.1077x over previous
#include <cuda_runtime.h>
#include <math.h>

#define BT 32
#define DIM 64
#define HW 4096
#define N2 131072
#define IMOFF 8388608
#define LNEPS 1e-5f

// ---------------- scratch (device globals; no allocations allowed) ----------------
__device__ __align__(16) float g_xc[(size_t)BT * HW * 128];   // 64 MB: LN'd conv input (pixel-major)
__device__ __align__(16) float g_x1r[(size_t)BT * DIM * HW];  // stage-1 output (real)
__device__ __align__(16) float g_x1i[(size_t)BT * DIM * HW];  // stage-1 output (imag)
__device__ __align__(16) float g_u[(size_t)8192 * 16 * 128];  // 67MB: u then h in-place, [n][t][128]
__device__ float g_ar[BT * DIM], g_ai[BT * DIM], g_fr[BT * DIM], g_fi[BT * DIM], g_sq[BT];

__device__ __forceinline__ float gelu_tanh(float x) {
    float t = 0.7978845608028654f * (x + 0.044715f * x * x * x);
    return 0.5f * x * (1.0f + tanhf(t));
}
__device__ __forceinline__ void fma4(float4& a, float s, float4 w) {
    a.x = fmaf(s, w.x, a.x); a.y = fmaf(s, w.y, a.y);
    a.z = fmaf(s, w.z, a.z); a.w = fmaf(s, w.w, a.w);
}
__device__ __forceinline__ float4 ld4(const float* p) { return *(const float4*)p; }
__device__ __forceinline__ float4 neg4(float4 v) { return make_float4(-v.x, -v.y, -v.z, -v.w); }

// ---------------- K0: per-(b,t,d) decay & forcing ----------------
__global__ void k_setup(const float* __restrict__ dt, const float* __restrict__ lam_re,
                        const float* __restrict__ lam_im) {
    int i = blockIdx.x * blockDim.x + threadIdx.x;
    if (i >= BT * DIM) return;
    int bt = i >> 6, d = i & 63;
    float dtv = dt[bt];
    float x = lam_re[d];
    float sp = (x > 20.f) ? x : log1pf(expf(x));
    float lr = -sp, li = lam_im[d];
    float er = expf(lr * dtv);
    float ar = er * cosf(li * dtv), ai = er * sinf(li * dtv);
    float den = lr * lr + li * li;
    g_ar[i] = ar; g_ai[i] = ai;
    g_fr[i] = ((ar - 1.f) * lr + ai * li) / den;
    g_fi[i] = (ai * lr - (ar - 1.f) * li) / den;
    if (d == 0) g_sq[bt] = 0.01f * sqrtf(dtv);
}

// ---------------- K1: spatial complex LayerNorm -> g_xc (channel-last) ----------------
__global__ void k_sln(const float* __restrict__ xr, const float* __restrict__ xi,
                      const float* __restrict__ w, const float* __restrict__ b) {
    __shared__ float sh[128][65];
    __shared__ float smu[64], srs[64];
    int t = threadIdx.x;
    int p0 = blockIdx.x * 64;
    int bt = p0 >> 12, hw0 = p0 & 4095;
    for (int r = 0; r < 32; r++) {
        int idx = t + 256 * r;
        int c = idx >> 6, p = idx & 63;
        float v = (c < 64) ? xr[((size_t)(bt * 64 + c)) * 4096 + hw0 + p]
                           : xi[((size_t)(bt * 64 + c - 64)) * 4096 + hw0 + p];
        sh[c][p] = v;
    }
    __syncthreads();
    int wid = t >> 5, lane = t & 31;
    if (wid < 8) {
        for (int pp = 0; pp < 8; pp++) {
            int p = wid * 8 + pp;
            float s = 0.f, s2 = 0.f;
            for (int cc = lane; cc < 128; cc += 32) {
                float v = sh[cc][p]; s += v; s2 += v * v;
            }
            for (int o = 16; o; o >>= 1) {
                s += __shfl_xor_sync(0xffffffffu, s, o);
                s2 += __shfl_xor_sync(0xffffffffu, s2, o);
            }
            if (lane == 0) {
                float mu = s * (1.f / 128.f);
                smu[p] = mu;
                srs[p] = rsqrtf(s2 * (1.f / 128.f) - mu * mu + LNEPS);
            }
        }
    }
    __syncthreads();
    for (int r = 0; r < 32; r++) {
        int idx = t + 256 * r;
        int p = idx >> 7, c = idx & 127;
        float v = (sh[c][p] - smu[p]) * srs[p] * w[c] + b[c];
        g_xc[((size_t)(p0 + p)) * 128 + c] = v;
    }
}

// ---------------- K2: 3x3 conv 128->128 + bias + residual -> x1 ----------------
__global__ void k_conv(const float* __restrict__ cw, const float* __restrict__ cb,
                       const float* __restrict__ xr, const float* __restrict__ xi) {
    __shared__ float in_sh[32][129];
    __shared__ float4 w4[32][32];
    int t = threadIdx.x;
    int w0 = blockIdx.x * 16, h0 = blockIdx.y * 8, bt = blockIdx.z;
    int lane = t & 31, cg = t >> 5;
    float4 acc[4][4];
    for (int k = 0; k < 4; k++) for (int q = 0; q < 4; q++) acc[k][q] = make_float4(0, 0, 0, 0);
    const float* img = g_xc + (size_t)bt * HW * 128;
    for (int ch = 0; ch < 4; ch++) {
        int ci0 = ch * 32;
        for (int tap = 0; tap < 9; tap++) {
            int dy = tap / 3 - 1, dx = tap % 3 - 1;
            __syncthreads();
            for (int r = 0; r < 4; r++) {
                int idx = t + 256 * r;
                int p = idx >> 3, c4 = idx & 7;
                int y = p >> 4, x = p & 15;
                int gh = h0 + y + dy, gw = w0 + x + dx;
                float4 v = make_float4(0, 0, 0, 0);
                if ((unsigned)gh < 64u && (unsigned)gw < 64u)
                    v = *(const float4*)(img + ((size_t)(gh * 64 + gw)) * 128 + ci0 + c4 * 4);
                in_sh[c4 * 4 + 0][p] = v.x; in_sh[c4 * 4 + 1][p] = v.y;
                in_sh[c4 * 4 + 2][p] = v.z; in_sh[c4 * 4 + 3][p] = v.w;
            }
            for (int r = 0; r < 4; r++) {
                int idx = t + 256 * r;
                int c = idx >> 5, j4 = idx & 31;
                w4[c][j4] = *(const float4*)(cw + ((size_t)(tap * 128 + ci0 + c)) * 128 + j4 * 4);
            }
            __syncthreads();
#pragma unroll 4
            for (int c = 0; c < 32; c++) {
                float iv0 = in_sh[c][lane], iv1 = in_sh[c][lane + 32];
                float iv2 = in_sh[c][lane + 64], iv3 = in_sh[c][lane + 96];
#pragma unroll
                for (int q = 0; q < 4; q++) {
                    float4 wv = w4[c][cg * 4 + q];
                    fma4(acc[0][q], iv0, wv);
                    fma4(acc[1][q], iv1, wv);
                    fma4(acc[2][q], iv2, wv);
                    fma4(acc[3][q], iv3, wv);
                }
            }
        }
    }
    for (int q = 0; q < 4; q++) {
        for (int m = 0; m < 4; m++) {
            int co = cg * 16 + q * 4 + m;
            float bias = cb[co];
            for (int k = 0; k < 4; k++) {
                int p = lane + 32 * k;
                int y = p >> 4, x = p & 15;
                float v = ((const float*)&acc[k][q])[m] + bias;
                if (co < 64) {
                    size_t gi = ((size_t)(bt * 64 + co)) * 4096 + (h0 + y) * 64 + (w0 + x);
                    g_x1r[gi] = v + xr[gi];
                } else {
                    size_t gi = ((size_t)(bt * 64 + co - 64)) * 4096 + (h0 + y) * 64 + (w0 + x);
                    g_x1i[gi] = v + xi[gi];
                }
            }
        }
    }
}

// ---------------- K3a: temporal LN + encode GEMM + forcing + noise -> g_u ----------------
// tile = 64 tokens (fixed bt, consecutive hw) x 128 cols. su aliases A after GEMM.
__global__ void k_enc(const float* __restrict__ ltw, const float* __restrict__ ltb,
                      const float* __restrict__ encr, const float* __restrict__ enci,
                      const float* __restrict__ sbr, const float* __restrict__ sbi,
                      const float* __restrict__ nzr, const float* __restrict__ nzi) {
    __shared__ float A[128][65];
    __shared__ float4 w4[16][32];
    __shared__ float smu[64], srs[64];
    int t = threadIdx.x;
    int t0 = blockIdx.x * 64;
    int bt = t0 >> 12, hw0 = t0 & 4095;
    int b = bt >> 4, tt = bt & 15;
    int token = t & 63, cg = t >> 6;
    // load tile (planar, coalesced)
    for (int r = 0; r < 32; r++) {
        int idx = t + 256 * r;
        int c = idx >> 6, tl = idx & 63;
        A[c][tl] = (c < 64) ? g_x1r[((size_t)(bt * 64 + c)) * 4096 + hw0 + tl]
                            : g_x1i[((size_t)(bt * 64 + c - 64)) * 4096 + hw0 + tl];
    }
    __syncthreads();
    // LN stats per token
    int wid = t >> 5, lane = t & 31;
    if (wid < 8) {
        for (int pp = 0; pp < 8; pp++) {
            int p = wid * 8 + pp;
            float s = 0.f, s2 = 0.f;
            for (int cc = lane; cc < 128; cc += 32) {
                float v = A[cc][p]; s += v; s2 += v * v;
            }
            for (int o = 16; o; o >>= 1) {
                s += __shfl_xor_sync(0xffffffffu, s, o);
                s2 += __shfl_xor_sync(0xffffffffu, s2, o);
            }
            if (lane == 0) {
                float mu = s * (1.f / 128.f);
                smu[p] = mu;
                srs[p] = rsqrtf(s2 * (1.f / 128.f) - mu * mu + LNEPS);
            }
        }
    }
    __syncthreads();
    // normalize in place
    for (int r = 0; r < 32; r++) {
        int idx = t + 256 * r;
        int p = idx >> 7, c = idx & 127;
        A[c][p] = (A[c][p] - smu[p]) * srs[p] * ltw[c] + ltb[c];
    }
    // GEMM: [64 tok x 128k] @ B[128k x 128] where B packs complex enc
    float4 acc[8];
    for (int q = 0; q < 8; q++) acc[q] = make_float4(0, 0, 0, 0);
    for (int kc = 0; kc < 8; kc++) {
        int ci0 = kc * 16;
        __syncthreads();
        for (int r = 0; r < 2; r++) {
            int idx = t + 256 * r;
            int kk = idx >> 5, j4 = idx & 31;
            int k = ci0 + kk;
            float4 v;
            if (k < 64) v = (j4 < 16) ? ld4(encr + k * 64 + j4 * 4)
                                      : ld4(enci + k * 64 + (j4 - 16) * 4);
            else {
                int k2 = k - 64;
                v = (j4 < 16) ? neg4(ld4(enci + k2 * 64 + j4 * 4))
                              : ld4(encr + k2 * 64 + (j4 - 16) * 4);
            }
            w4[kk][j4] = v;
        }
        __syncthreads();
#pragma unroll
        for (int kk = 0; kk < 16; kk++) {
            float tv = A[ci0 + kk][token];
#pragma unroll
            for (int q = 0; q < 8; q++) fma4(acc[q], tv, w4[kk][cg * 8 + q]);
        }
    }
    __syncthreads();
    // stage (+src bias) into su (aliases A)
    float* su = &A[0][0];
    for (int q = 0; q < 8; q++)
        for (int m = 0; m < 4; m++) {
            int j = cg * 32 + q * 4 + m;
            float bv = (j < 64) ? sbr[j] : sbi[j - 64];
            su[j * 65 + token] = ((const float*)&acc[q])[m] + bv;
        }
    __syncthreads();
    // epilogue: forcing + noise, write u[n][t][128]
    int e = t & 63, tg = t >> 6;
    int ai_ = bt * 64 + e;
    float fr = g_fr[ai_], fi = g_fi[ai_], sq = g_sq[bt];
    for (int k = 0; k < 16; k++) {
        int tk = tg * 16 + k;
        int n = b * 4096 + hw0 + tk;
        size_t ub = ((size_t)n * 16 + tt) * 128;
        float ur = su[e * 65 + tk], ui = su[(e + 64) * 65 + tk];
        size_t nb = ((size_t)n * 16 + tt) * 64 + e;
        g_u[ub + e]      = ur * fr - ui * fi + sq * nzr[nb];
        g_u[ub + 64 + e] = ur * fi + ui * fr + sq * nzi[nb];
    }
}

// ---------------- K3b: in-place 16-step scan over g_u ----------------
__global__ void k_scan() {
    int t = threadIdx.x;
    int e = t & 63;
    int n = blockIdx.x * 4 + (t >> 6);
    int b = n >> 12;
    float hr = 0.f, hi = 0.f;
    for (int tt = 0; tt < 16; tt++) {
        size_t base = ((size_t)n * 16 + tt) * 128;
        float ur = g_u[base + e], ui = g_u[base + 64 + e];
        int ai_ = (b * 16 + tt) * 64 + e;
        float ar = g_ar[ai_], aiv = g_ai[ai_];
        float nhr = ar * hr - aiv * hi + ur;
        float nhi = ar * hi + aiv * hr + ui;
        hr = nhr; hi = nhi;
        g_u[base + e] = hr; g_u[base + 64 + e] = hi;
    }
}

// ---------------- K3c: decode GEMM + residual -> d_out (also imag copy) ----------------
__global__ void k_dec(const float* __restrict__ decr, const float* __restrict__ deci,
                      float* __restrict__ out) {
    __shared__ float A[32][65];
    __shared__ float4 w4[32][16];
    __shared__ float sdr[64][65];
    int t = threadIdx.x;
    int t0 = blockIdx.x * 64;
    int bt = t0 >> 12, hw0 = t0 & 4095;
    int b = bt >> 4, tt = bt & 15;
    int token = t & 63, cg = t >> 6;
    float4 acc[4];
    for (int q = 0; q < 4; q++) acc[q] = make_float4(0, 0, 0, 0);
    for (int kc = 0; kc < 4; kc++) {
        int ci0 = kc * 32;
        __syncthreads();
        for (int r = 0; r < 8; r++) {
            int idx = t + 256 * r;
            int kk = idx & 31, tl = idx >> 5;
            A[kk][tl] = g_u[((size_t)(b * 4096 + hw0 + tl) * 16 + tt) * 128 + ci0 + kk];
        }
        for (int r = 0; r < 2; r++) {
            int idx = t + 256 * r;
            int kk = idx >> 4, j4 = idx & 15;
            int k = ci0 + kk;
            float4 v = (k < 64) ? ld4(decr + k * 64 + j4 * 4)
                                : neg4(ld4(deci + (k - 64) * 64 + j4 * 4));
            w4[kk][j4] = v;
        }
        __syncthreads();
#pragma unroll 8
        for (int kk = 0; kk < 32; kk++) {
            float tv = A[kk][token];
#pragma unroll
            for (int q = 0; q < 4; q++) fma4(acc[q], tv, w4[kk][cg * 4 + q]);
        }
    }
    __syncthreads();
    for (int q = 0; q < 4; q++)
        for (int m = 0; m < 4; m++) {
            int d = cg * 16 + q * 4 + m;
            sdr[d][token] = ((const float*)&acc[q])[m];
        }
    __syncthreads();
    int tk = t & 63, d0 = t >> 6;
    for (int k = 0; k < 16; k++) {
        int d = d0 + 4 * k;
        size_t gi = ((size_t)(bt * 64 + d)) * 4096 + hw0 + tk;
        out[gi] = g_x1r[gi] + sdr[d][tk];
        out[IMOFF + gi] = g_x1i[gi];
    }
}

// ---------------- K4: fused MoE (gates + GEMM1 + gelu*gate + GEMM2 + out +=) ----------------
__global__ void k_moe(const float* __restrict__ rw, const float* __restrict__ rb,
                      const float* __restrict__ w1, const float* __restrict__ b1,
                      const float* __restrict__ w2, const float* __restrict__ b2,
                      float* __restrict__ out) {
    extern __shared__ float ds[];
    float* tok = ds;                       // [128][64]
    float* hs  = ds + 8192;                // [128][64]
    float4* w4 = (float4*)(ds + 16384);    // [32][32] float4
    float* gsh = ds + 20480;               // [4][64]
    int t = threadIdx.x;
    int t0 = blockIdx.x * 64;
    int bt = t0 >> 12, hw0 = t0 & 4095;
    int token = t & 63, cg = t >> 6;
    // load token tile
    for (int r = 0; r < 32; r++) {
        int idx = t + 256 * r;
        int c = idx >> 6, tl = idx & 63;
        float v = (c < 64) ? out[((size_t)(bt * 64 + c)) * 4096 + hw0 + tl]
                           : out[IMOFF + ((size_t)(bt * 64 + c - 64)) * 4096 + hw0 + tl];
        tok[c * 64 + tl] = v;
    }
    __syncthreads();
    // gates
    if (t < 64) {
        float l0 = rb[0], l1 = rb[1], l2 = rb[2], l3 = rb[3];
        for (int c = 0; c < 128; c++) {
            float v = tok[c * 64 + t];
            float4 wv = ld4(rw + c * 4);
            l0 = fmaf(v, wv.x, l0); l1 = fmaf(v, wv.y, l1);
            l2 = fmaf(v, wv.z, l2); l3 = fmaf(v, wv.w, l3);
        }
        float m = fmaxf(fmaxf(l0, l1), fmaxf(l2, l3));
        float e0 = expf(l0 - m), e1 = expf(l1 - m), e2 = expf(l2 - m), e3 = expf(l3 - m);
        float inv = 1.f / (e0 + e1 + e2 + e3);
        gsh[0 * 64 + t] = e0 * inv; gsh[1 * 64 + t] = e1 * inv;
        gsh[2 * 64 + t] = e2 * inv; gsh[3 * 64 + t] = e3 * inv;
    }
    __syncthreads();
    float4 acc2[8];
    for (int q = 0; q < 8; q++) acc2[q] = make_float4(0, 0, 0, 0);
    for (int e = 0; e < 4; e++) {
        float4 acc1[8];
        for (int q = 0; q < 8; q++) acc1[q] = make_float4(0, 0, 0, 0);
        // GEMM1: tok @ w1[e]
        for (int kc = 0; kc < 4; kc++) {
            int ci0 = kc * 32;
            __syncthreads();
            for (int r = 0; r < 4; r++) {
                int idx = t + 256 * r;
                int kk = idx >> 5, j4 = idx & 31;
                w4[kk * 32 + j4] = ld4(w1 + (size_t)e * 16384 + (ci0 + kk) * 128 + j4 * 4);
            }
            __syncthreads();
#pragma unroll 4
            for (int kk = 0; kk < 32; kk++) {
                float tv = tok[(ci0 + kk) * 64 + token];
#pragma unroll
                for (int q = 0; q < 8; q++) fma4(acc1[q], tv, w4[kk * 32 + cg * 8 + q]);
            }
        }
        float gate = gsh[e * 64 + token];
        for (int q = 0; q < 8; q++)
            for (int m = 0; m < 4; m++) {
                int j = cg * 32 + q * 4 + m;
                float v = ((const float*)&acc1[q])[m] + b1[e * 128 + j];
                hs[j * 64 + token] = gelu_tanh(v) * gate;
            }
        __syncthreads();
        // GEMM2: hs @ w2[e], accumulate across experts
        for (int kc = 0; kc < 4; kc++) {
            int ci0 = kc * 32;
            __syncthreads();
            for (int r = 0; r < 4; r++) {
                int idx = t + 256 * r;
                int kk = idx >> 5, j4 = idx & 31;
                w4[kk * 32 + j4] = ld4(w2 + (size_t)e * 16384 + (ci0 + kk) * 128 + j4 * 4);
            }
            __syncthreads();
#pragma unroll 4
            for (int kk = 0; kk < 32; kk++) {
                float tv = hs[(ci0 + kk) * 64 + token];
#pragma unroll
                for (int q = 0; q < 8; q++) fma4(acc2[q], tv, w4[kk * 32 + cg * 8 + q]);
            }
        }
    }
    // epilogue
    float g0 = gsh[0 * 64 + token], g1 = gsh[1 * 64 + token];
    float g2 = gsh[2 * 64 + token], g3 = gsh[3 * 64 + token];
    int hw = hw0 + token;
    for (int q = 0; q < 8; q++)
        for (int m = 0; m < 4; m++) {
            int o = cg * 32 + q * 4 + m;
            float bterm = g0 * b2[o] + g1 * b2[128 + o] + g2 * b2[256 + o] + g3 * b2[384 + o];
            float delta = ((const float*)&acc2[q])[m] + bterm;
            size_t gi = (o < 64) ? ((size_t)(bt * 64 + o)) * 4096 + hw
                                 : IMOFF + ((size_t)(bt * 64 + o - 64)) * 4096 + hw;
            out[gi] += delta;
        }
}

extern "C" void kernel_launch(void* const* d_in, const int* in_sizes, int n_in,
                              void* d_out, int out_size) {
    const float* x_real = (const float*)d_in[0];
    const float* x_imag = (const float*)d_in[1];
    const float* dt     = (const float*)d_in[2];
    const float* nz_r   = (const float*)d_in[3];
    const float* nz_i   = (const float*)d_in[4];
    const float* ln_s_w = (const float*)d_in[5];
    const float* ln_s_b = (const float*)d_in[6];
    const float* conv_w = (const float*)d_in[7];
    const float* conv_b = (const float*)d_in[8];
    const float* ln_t_w = (const float*)d_in[9];
    const float* ln_t_b = (const float*)d_in[10];
    const float* lam_re = (const float*)d_in[11];
    const float* lam_im = (const float*)d_in[12];
    const float* sb_re  = (const float*)d_in[13];
    const float* sb_im  = (const float*)d_in[14];
    const float* enc_re = (const float*)d_in[15];
    const float* enc_im = (const float*)d_in[16];
    const float* dec_re = (const float*)d_in[17];
    const float* dec_im = (const float*)d_in[18];
    const float* rw     = (const float*)d_in[19];
    const float* rb     = (const float*)d_in[20];
    const float* w1     = (const float*)d_in[21];
    const float* b1     = (const float*)d_in[22];
    const float* w2     = (const float*)d_in[23];
    const float* b2     = (const float*)d_in[24];
    float* out = (float*)d_out;

    cudaFuncSetAttribute(k_moe, cudaFuncAttributeMaxDynamicSharedMemorySize, 84 * 1024);

    k_setup<<<8, 256>>>(dt, lam_re, lam_im);
    k_sln<<<2048, 256>>>(x_real, x_imag, ln_s_w, ln_s_b);
    k_conv<<<dim3(4, 8, 32), 256>>>(conv_w, conv_b, x_real, x_imag);
    k_enc<<<2048, 256>>>(ln_t_w, ln_t_b, enc_re, enc_im, sb_re, sb_im, nz_r, nz_i);
    k_scan<<<2048, 256>>>();
    k_dec<<<2048, 256>>>(dec_re, dec_im, out);
    k_moe<<<2048, 256, 84 * 1024>>>(rw, rb, w1, b1, w2, b2, out);
}

// round 4
// speedup vs baseline: 2.9653x; 2.6769x over previous
#include <cuda_runtime.h>
#include <math.h>
#include <stdint.h>

#define BT 32
#define DIM 64
#define HW 4096
#define N2 131072
#define IMOFF 8388608
#define LNEPS 1e-5f

// ---------------- scratch ----------------
__device__ __align__(16) float g_xc[(size_t)BT * HW * 128];   // LN'd conv input (pixel-major, tf32-rounded)
__device__ __align__(16) float g_x1r[(size_t)BT * DIM * HW];
__device__ __align__(16) float g_x1i[(size_t)BT * DIM * HW];
__device__ __align__(16) float g_u[(size_t)8192 * 16 * 128];  // u then h in-place, [n][t][128]
__device__ float g_ar[BT * DIM], g_ai[BT * DIM], g_fr[BT * DIM], g_fi[BT * DIM], g_sq[BT];

__device__ __forceinline__ float gelu_tanh(float x) {
    float t = 0.7978845608028654f * (x + 0.044715f * x * x * x);
    return 0.5f * x * (1.0f + tanhf(t));
}
__device__ __forceinline__ void fma4(float4& a, float s, float4 w) {
    a.x = fmaf(s, w.x, a.x); a.y = fmaf(s, w.y, a.y);
    a.z = fmaf(s, w.z, a.z); a.w = fmaf(s, w.w, a.w);
}
__device__ __forceinline__ float4 ld4(const float* p) { return *(const float4*)p; }
__device__ __forceinline__ float4 neg4(float4 v) { return make_float4(-v.x, -v.y, -v.z, -v.w); }
__device__ __forceinline__ uint32_t f2tf32(float f) {
    uint32_t u; asm("cvt.rna.tf32.f32 %0, %1;" : "=r"(u) : "f"(f)); return u;
}
__device__ __forceinline__ void mma_tf32(float4& c, uint32_t a0, uint32_t a1, uint32_t a2,
                                         uint32_t a3, uint32_t b0, uint32_t b1) {
    asm volatile("mma.sync.aligned.m16n8k8.row.col.f32.tf32.tf32.f32 "
                 "{%0,%1,%2,%3}, {%4,%5,%6,%7}, {%8,%9}, {%0,%1,%2,%3};"
                 : "+f"(c.x), "+f"(c.y), "+f"(c.z), "+f"(c.w)
                 : "r"(a0), "r"(a1), "r"(a2), "r"(a3), "r"(b0), "r"(b1));
}

// ---------------- K0: per-(b,t,d) decay & forcing ----------------
__global__ void k_setup(const float* __restrict__ dt, const float* __restrict__ lam_re,
                        const float* __restrict__ lam_im) {
    int i = blockIdx.x * blockDim.x + threadIdx.x;
    if (i >= BT * DIM) return;
    int bt = i >> 6, d = i & 63;
    float dtv = dt[bt];
    float x = lam_re[d];
    float sp = (x > 20.f) ? x : log1pf(expf(x));
    float lr = -sp, li = lam_im[d];
    float er = expf(lr * dtv);
    float ar = er * cosf(li * dtv), ai = er * sinf(li * dtv);
    float den = lr * lr + li * li;
    g_ar[i] = ar; g_ai[i] = ai;
    g_fr[i] = ((ar - 1.f) * lr + ai * li) / den;
    g_fi[i] = (ai * lr - (ar - 1.f) * li) / den;
    if (d == 0) g_sq[bt] = 0.01f * sqrtf(dtv);
}

// ---------------- K1: spatial complex LayerNorm -> g_xc (tf32-rounded) ----------------
__global__ void k_sln(const float* __restrict__ xr, const float* __restrict__ xi,
                      const float* __restrict__ w, const float* __restrict__ b) {
    __shared__ float sh[128][65];
    __shared__ float smu[64], srs[64];
    int t = threadIdx.x;
    int p0 = blockIdx.x * 64;
    int bt = p0 >> 12, hw0 = p0 & 4095;
    for (int r = 0; r < 32; r++) {
        int idx = t + 256 * r;
        int c = idx >> 6, p = idx & 63;
        float v = (c < 64) ? xr[((size_t)(bt * 64 + c)) * 4096 + hw0 + p]
                           : xi[((size_t)(bt * 64 + c - 64)) * 4096 + hw0 + p];
        sh[c][p] = v;
    }
    __syncthreads();
    int wid = t >> 5, lane = t & 31;
    if (wid < 8) {
        for (int pp = 0; pp < 8; pp++) {
            int p = wid * 8 + pp;
            float s = 0.f, s2 = 0.f;
            for (int cc = lane; cc < 128; cc += 32) {
                float v = sh[cc][p]; s += v; s2 += v * v;
            }
            for (int o = 16; o; o >>= 1) {
                s += __shfl_xor_sync(0xffffffffu, s, o);
                s2 += __shfl_xor_sync(0xffffffffu, s2, o);
            }
            if (lane == 0) {
                float mu = s * (1.f / 128.f);
                smu[p] = mu;
                srs[p] = rsqrtf(s2 * (1.f / 128.f) - mu * mu + LNEPS);
            }
        }
    }
    __syncthreads();
    for (int r = 0; r < 32; r++) {
        int idx = t + 256 * r;
        int p = idx >> 7, c = idx & 127;
        float v = (sh[c][p] - smu[p]) * srs[p] * w[c] + b[c];
        g_xc[((size_t)(p0 + p)) * 128 + c] = __uint_as_float(f2tf32(v));
    }
}

// ---------------- K2: 3x3 conv via tf32 mma, + bias + residual -> x1 ----------------
// block tile: 128 pixels (2 rows x 64 w) x 128 co. 8 warps: wm(4) x wn(2), 32px x 64co each.
#define CONV_ASTR 36
#define CONV_BSTR 136
__global__ void k_conv(const float* __restrict__ cw, const float* __restrict__ cb,
                       const float* __restrict__ xr, const float* __restrict__ xi) {
    extern __shared__ uint32_t cs[];
    uint32_t* A = cs;                  // [264][36]  (4 halo rows x 66 x, ci chunk 32)
    uint32_t* B = cs + 264 * CONV_ASTR;// [32][136]
    float* Cst = (float*)cs;           // epilogue stage [128 co][130]
    int t = threadIdx.x;
    int h0 = blockIdx.x * 2, bt = blockIdx.y;
    int wrp = t >> 5, lane = t & 31;
    int wm = wrp & 3, wn = wrp >> 2;
    int qr = lane >> 2, qc = lane & 3;
    float4 acc[2][8];
#pragma unroll
    for (int i = 0; i < 2; i++)
#pragma unroll
        for (int j = 0; j < 8; j++) acc[i][j] = make_float4(0, 0, 0, 0);

    for (int kc = 0; kc < 4; kc++) {
        int ci0 = kc * 32;
        __syncthreads();
        // load halo A tile: rows gh = h0-1 .. h0+2, x = -1..64
        for (int r = 0; r < 4; r++) {
            int gh = h0 + r - 1;
            for (int idx = t; idx < 2112; idx += 256) {
                int xx = idx >> 5, c = idx & 31;
                int gw = xx - 1;
                float v = 0.f;
                if ((unsigned)gh < 64u && (unsigned)gw < 64u)
                    v = g_xc[((size_t)(bt * 4096 + gh * 64 + gw)) * 128 + ci0 + c];
                A[(r * 66 + xx) * CONV_ASTR + c] = __float_as_uint(v);
            }
        }
        for (int tap = 0; tap < 9; tap++) {
            int dy = tap / 3 - 1, dx = tap % 3 - 1;
            __syncthreads();
            for (int idx = t; idx < 4096; idx += 256) {
                int kk = idx >> 7, co = idx & 127;
                B[kk * CONV_BSTR + co] = f2tf32(cw[((size_t)(tap * 128 + ci0 + kk)) * 128 + co]);
            }
            __syncthreads();
            int prs[4];
#pragma unroll
            for (int i = 0; i < 4; i++) {
                int m = wm * 32 + i * 8 + qr;
                int y = m >> 6, x = m & 63;
                prs[i] = (y + dy + 1) * 66 + (x + dx + 1);
            }
#pragma unroll
            for (int ks = 0; ks < 4; ks++) {
                int acol = ks * 8 + qc;
                uint32_t af[4][2];
#pragma unroll
                for (int i = 0; i < 4; i++) {
                    af[i][0] = A[prs[i] * CONV_ASTR + acol];
                    af[i][1] = A[prs[i] * CONV_ASTR + acol + 4];
                }
                int brow0 = (ks * 8 + qc) * CONV_BSTR;
                int brow1 = brow0 + 4 * CONV_BSTR;
#pragma unroll
                for (int nt = 0; nt < 8; nt++) {
                    int co = wn * 64 + nt * 8 + qr;
                    uint32_t b0 = B[brow0 + co], b1 = B[brow1 + co];
                    mma_tf32(acc[0][nt], af[0][0], af[1][0], af[0][1], af[1][1], b0, b1);
                    mma_tf32(acc[1][nt], af[2][0], af[3][0], af[2][1], af[3][1], b0, b1);
                }
            }
        }
    }
    __syncthreads();
#pragma unroll
    for (int mt = 0; mt < 2; mt++)
#pragma unroll
        for (int nt = 0; nt < 8; nt++) {
            int m0 = wm * 32 + mt * 16 + qr;
            int n0 = wn * 64 + nt * 8 + 2 * qc;
            float4 c = acc[mt][nt];
            Cst[n0 * 130 + m0] = c.x;
            Cst[(n0 + 1) * 130 + m0] = c.y;
            Cst[n0 * 130 + m0 + 8] = c.z;
            Cst[(n0 + 1) * 130 + m0 + 8] = c.w;
        }
    __syncthreads();
    int p = t & 127, og = t >> 7;
    size_t pb = (size_t)h0 * 64 + p;
    for (int j = 0; j < 64; j++) {
        int co = og * 64 + j;
        float v = Cst[co * 130 + p] + cb[co];
        if (co < 64) {
            size_t gi = ((size_t)(bt * 64 + co)) * 4096 + pb;
            g_x1r[gi] = v + xr[gi];
        } else {
            size_t gi = ((size_t)(bt * 64 + co - 64)) * 4096 + pb;
            g_x1i[gi] = v + xi[gi];
        }
    }
}

// ---------------- K3a: temporal LN + encode GEMM + forcing + noise -> g_u ----------------
__global__ void k_enc(const float* __restrict__ ltw, const float* __restrict__ ltb,
                      const float* __restrict__ encr, const float* __restrict__ enci,
                      const float* __restrict__ sbr, const float* __restrict__ sbi,
                      const float* __restrict__ nzr, const float* __restrict__ nzi) {
    __shared__ float A[128][65];
    __shared__ float4 w4[16][32];
    __shared__ float smu[64], srs[64];
    int t = threadIdx.x;
    int t0 = blockIdx.x * 64;
    int bt = t0 >> 12, hw0 = t0 & 4095;
    int b = bt >> 4, tt = bt & 15;
    int token = t & 63, cg = t >> 6;
    for (int r = 0; r < 32; r++) {
        int idx = t + 256 * r;
        int c = idx >> 6, tl = idx & 63;
        A[c][tl] = (c < 64) ? g_x1r[((size_t)(bt * 64 + c)) * 4096 + hw0 + tl]
                            : g_x1i[((size_t)(bt * 64 + c - 64)) * 4096 + hw0 + tl];
    }
    __syncthreads();
    int wid = t >> 5, lane = t & 31;
    if (wid < 8) {
        for (int pp = 0; pp < 8; pp++) {
            int p = wid * 8 + pp;
            float s = 0.f, s2 = 0.f;
            for (int cc = lane; cc < 128; cc += 32) {
                float v = A[cc][p]; s += v; s2 += v * v;
            }
            for (int o = 16; o; o >>= 1) {
                s += __shfl_xor_sync(0xffffffffu, s, o);
                s2 += __shfl_xor_sync(0xffffffffu, s2, o);
            }
            if (lane == 0) {
                float mu = s * (1.f / 128.f);
                smu[p] = mu;
                srs[p] = rsqrtf(s2 * (1.f / 128.f) - mu * mu + LNEPS);
            }
        }
    }
    __syncthreads();
    for (int r = 0; r < 32; r++) {
        int idx = t + 256 * r;
        int p = idx >> 7, c = idx & 127;
        A[c][p] = (A[c][p] - smu[p]) * srs[p] * ltw[c] + ltb[c];
    }
    float4 acc[8];
    for (int q = 0; q < 8; q++) acc[q] = make_float4(0, 0, 0, 0);
    for (int kc = 0; kc < 8; kc++) {
        int ci0 = kc * 16;
        __syncthreads();
        for (int r = 0; r < 2; r++) {
            int idx = t + 256 * r;
            int kk = idx >> 5, j4 = idx & 31;
            int k = ci0 + kk;
            float4 v;
            if (k < 64) v = (j4 < 16) ? ld4(encr + k * 64 + j4 * 4)
                                      : ld4(enci + k * 64 + (j4 - 16) * 4);
            else {
                int k2 = k - 64;
                v = (j4 < 16) ? neg4(ld4(enci + k2 * 64 + j4 * 4))
                              : ld4(encr + k2 * 64 + (j4 - 16) * 4);
            }
            w4[kk][j4] = v;
        }
        __syncthreads();
#pragma unroll
        for (int kk = 0; kk < 16; kk++) {
            float tv = A[ci0 + kk][token];
#pragma unroll
            for (int q = 0; q < 8; q++) fma4(acc[q], tv, w4[kk][cg * 8 + q]);
        }
    }
    __syncthreads();
    float* su = &A[0][0];
    for (int q = 0; q < 8; q++)
        for (int m = 0; m < 4; m++) {
            int j = cg * 32 + q * 4 + m;
            float bv = (j < 64) ? sbr[j] : sbi[j - 64];
            su[j * 65 + token] = ((const float*)&acc[q])[m] + bv;
        }
    __syncthreads();
    int e = t & 63, tg = t >> 6;
    int ai_ = bt * 64 + e;
    float fr = g_fr[ai_], fi = g_fi[ai_], sq = g_sq[bt];
    for (int k = 0; k < 16; k++) {
        int tk = tg * 16 + k;
        int n = b * 4096 + hw0 + tk;
        size_t ub = ((size_t)n * 16 + tt) * 128;
        float ur = su[e * 65 + tk], ui = su[(e + 64) * 65 + tk];
        size_t nb = ((size_t)n * 16 + tt) * 64 + e;
        g_u[ub + e]      = ur * fr - ui * fi + sq * nzr[nb];
        g_u[ub + 64 + e] = ur * fi + ui * fr + sq * nzi[nb];
    }
}

// ---------------- K3b: in-place 16-step scan over g_u ----------------
__global__ void k_scan() {
    int t = threadIdx.x;
    int e = t & 63;
    int n = blockIdx.x * 4 + (t >> 6);
    int b = n >> 12;
    float hr = 0.f, hi = 0.f;
    for (int tt = 0; tt < 16; tt++) {
        size_t base = ((size_t)n * 16 + tt) * 128;
        float ur = g_u[base + e], ui = g_u[base + 64 + e];
        int ai_ = (b * 16 + tt) * 64 + e;
        float ar = g_ar[ai_], aiv = g_ai[ai_];
        float nhr = ar * hr - aiv * hi + ur;
        float nhi = ar * hi + aiv * hr + ui;
        hr = nhr; hi = nhi;
        g_u[base + e] = hr; g_u[base + 64 + e] = hi;
    }
}

// ---------------- K3c: decode GEMM + residual -> d_out ----------------
__global__ void k_dec(const float* __restrict__ decr, const float* __restrict__ deci,
                      float* __restrict__ out) {
    __shared__ float A[32][65];
    __shared__ float4 w4[32][16];
    __shared__ float sdr[64][65];
    int t = threadIdx.x;
    int t0 = blockIdx.x * 64;
    int bt = t0 >> 12, hw0 = t0 & 4095;
    int b = bt >> 4, tt = bt & 15;
    int token = t & 63, cg = t >> 6;
    float4 acc[4];
    for (int q = 0; q < 4; q++) acc[q] = make_float4(0, 0, 0, 0);
    for (int kc = 0; kc < 4; kc++) {
        int ci0 = kc * 32;
        __syncthreads();
        for (int r = 0; r < 8; r++) {
            int idx = t + 256 * r;
            int kk = idx & 31, tl = idx >> 5;
            A[kk][tl] = g_u[((size_t)(b * 4096 + hw0 + tl) * 16 + tt) * 128 + ci0 + kk];
        }
        for (int r = 0; r < 2; r++) {
            int idx = t + 256 * r;
            int kk = idx >> 4, j4 = idx & 15;
            int k = ci0 + kk;
            float4 v = (k < 64) ? ld4(decr + k * 64 + j4 * 4)
                                : neg4(ld4(deci + (k - 64) * 64 + j4 * 4));
            w4[kk][j4] = v;
        }
        __syncthreads();
#pragma unroll 8
        for (int kk = 0; kk < 32; kk++) {
            float tv = A[kk][token];
#pragma unroll
            for (int q = 0; q < 4; q++) fma4(acc[q], tv, w4[kk][cg * 4 + q]);
        }
    }
    __syncthreads();
    for (int q = 0; q < 4; q++)
        for (int m = 0; m < 4; m++) {
            int d = cg * 16 + q * 4 + m;
            sdr[d][token] = ((const float*)&acc[q])[m];
        }
    __syncthreads();
    int tk = t & 63, d0 = t >> 6;
    for (int k = 0; k < 16; k++) {
        int d = d0 + 4 * k;
        size_t gi = ((size_t)(bt * 64 + d)) * 4096 + hw0 + tk;
        out[gi] = g_x1r[gi] + sdr[d][tk];
        out[IMOFF + gi] = g_x1i[gi];
    }
}

// ---------------- K4: fused MoE with tf32 mma ----------------
// block = 128 tokens x 128 outputs; 8 warps wm(4) x wn(2).
#define MOE_ASTR 132
#define MOE_BSTR 136
__global__ void k_moe(const float* __restrict__ rw, const float* __restrict__ rb,
                      const float* __restrict__ w1, const float* __restrict__ b1,
                      const float* __restrict__ w2, const float* __restrict__ b2,
                      float* __restrict__ out) {
    extern __shared__ uint32_t ms[];
    uint32_t* A  = ms;                         // [128][132] tokens (tf32)
    uint32_t* HS = ms + 128 * MOE_ASTR;        // [128][132] hidden (tf32); reused as C stage
    uint32_t* B  = ms + 2 * 128 * MOE_ASTR;    // [32][136]
    float* G     = (float*)(ms + 2 * 128 * MOE_ASTR + 32 * MOE_BSTR);  // [4][128]
    float* Cst   = (float*)HS;                 // [128 o][130]
    int t = threadIdx.x;
    int t0 = blockIdx.x * 128;
    int bt = t0 >> 12, hw0 = t0 & 4095;
    int wrp = t >> 5, lane = t & 31;
    int wm = wrp & 3, wn = wrp >> 2;
    int qr = lane >> 2, qc = lane & 3;

    for (int r = 0; r < 64; r++) {
        int idx = t + 256 * r;
        int c = idx >> 7, tl = idx & 127;
        float v = (c < 64) ? out[((size_t)(bt * 64 + c)) * 4096 + hw0 + tl]
                           : out[IMOFF + ((size_t)(bt * 64 + c - 64)) * 4096 + hw0 + tl];
        A[tl * MOE_ASTR + c] = f2tf32(v);
    }
    __syncthreads();
    if (t < 128) {
        float l0 = rb[0], l1 = rb[1], l2 = rb[2], l3 = rb[3];
        for (int c = 0; c < 128; c++) {
            float v = __uint_as_float(A[t * MOE_ASTR + c]);
            float4 wv = ld4(rw + c * 4);
            l0 = fmaf(v, wv.x, l0); l1 = fmaf(v, wv.y, l1);
            l2 = fmaf(v, wv.z, l2); l3 = fmaf(v, wv.w, l3);
        }
        float m = fmaxf(fmaxf(l0, l1), fmaxf(l2, l3));
        float e0 = expf(l0 - m), e1 = expf(l1 - m), e2 = expf(l2 - m), e3 = expf(l3 - m);
        float inv = 1.f / (e0 + e1 + e2 + e3);
        G[0 * 128 + t] = e0 * inv; G[1 * 128 + t] = e1 * inv;
        G[2 * 128 + t] = e2 * inv; G[3 * 128 + t] = e3 * inv;
    }
    float4 acc2[2][8];
#pragma unroll
    for (int i = 0; i < 2; i++)
#pragma unroll
        for (int j = 0; j < 8; j++) acc2[i][j] = make_float4(0, 0, 0, 0);

    for (int e = 0; e < 4; e++) {
        float4 acc1[2][8];
#pragma unroll
        for (int i = 0; i < 2; i++)
#pragma unroll
            for (int j = 0; j < 8; j++) acc1[i][j] = make_float4(0, 0, 0, 0);
        // GEMM1: A @ w1[e]
        for (int kc = 0; kc < 4; kc++) {
            int ci0 = kc * 32;
            __syncthreads();
            for (int idx = t; idx < 4096; idx += 256) {
                int kk = idx >> 7, j = idx & 127;
                B[kk * MOE_BSTR + j] = f2tf32(w1[(size_t)e * 16384 + (ci0 + kk) * 128 + j]);
            }
            __syncthreads();
#pragma unroll
            for (int ks = 0; ks < 4; ks++) {
                int acol = ci0 + ks * 8 + qc;
                uint32_t af[4][2];
#pragma unroll
                for (int i = 0; i < 4; i++) {
                    int row = wm * 32 + i * 8 + qr;
                    af[i][0] = A[row * MOE_ASTR + acol];
                    af[i][1] = A[row * MOE_ASTR + acol + 4];
                }
                int br0 = (ks * 8 + qc) * MOE_BSTR, br1 = br0 + 4 * MOE_BSTR;
#pragma unroll
                for (int nt = 0; nt < 8; nt++) {
                    int j = wn * 64 + nt * 8 + qr;
                    uint32_t b0 = B[br0 + j], b1 = B[br1 + j];
                    mma_tf32(acc1[0][nt], af[0][0], af[1][0], af[0][1], af[1][1], b0, b1);
                    mma_tf32(acc1[1][nt], af[2][0], af[3][0], af[2][1], af[3][1], b0, b1);
                }
            }
        }
        __syncthreads();
        // epilogue1: bias + gelu * gate -> HS (tf32)
#pragma unroll
        for (int mt = 0; mt < 2; mt++)
#pragma unroll
            for (int nt = 0; nt < 8; nt++) {
                int tok0 = wm * 32 + mt * 16 + qr;
                int j0 = wn * 64 + nt * 8 + 2 * qc;
                float4 c = acc1[mt][nt];
                float b1v0 = b1[e * 128 + j0], b1v1 = b1[e * 128 + j0 + 1];
                float g0 = G[e * 128 + tok0], g8 = G[e * 128 + tok0 + 8];
                HS[tok0 * MOE_ASTR + j0]       = f2tf32(gelu_tanh(c.x + b1v0) * g0);
                HS[tok0 * MOE_ASTR + j0 + 1]   = f2tf32(gelu_tanh(c.y + b1v1) * g0);
                HS[(tok0 + 8) * MOE_ASTR + j0]     = f2tf32(gelu_tanh(c.z + b1v0) * g8);
                HS[(tok0 + 8) * MOE_ASTR + j0 + 1] = f2tf32(gelu_tanh(c.w + b1v1) * g8);
            }
        // GEMM2: HS @ w2[e] -> acc2
        for (int kc = 0; kc < 4; kc++) {
            int ci0 = kc * 32;
            __syncthreads();
            for (int idx = t; idx < 4096; idx += 256) {
                int kk = idx >> 7, j = idx & 127;
                B[kk * MOE_BSTR + j] = f2tf32(w2[(size_t)e * 16384 + (ci0 + kk) * 128 + j]);
            }
            __syncthreads();
#pragma unroll
            for (int ks = 0; ks < 4; ks++) {
                int acol = ci0 + ks * 8 + qc;
                uint32_t af[4][2];
#pragma unroll
                for (int i = 0; i < 4; i++) {
                    int row = wm * 32 + i * 8 + qr;
                    af[i][0] = HS[row * MOE_ASTR + acol];
                    af[i][1] = HS[row * MOE_ASTR + acol + 4];
                }
                int br0 = (ks * 8 + qc) * MOE_BSTR, br1 = br0 + 4 * MOE_BSTR;
#pragma unroll
                for (int nt = 0; nt < 8; nt++) {
                    int j = wn * 64 + nt * 8 + qr;
                    uint32_t b0 = B[br0 + j], b1v = B[br1 + j];
                    mma_tf32(acc2[0][nt], af[0][0], af[1][0], af[0][1], af[1][1], b0, b1v);
                    mma_tf32(acc2[1][nt], af[2][0], af[3][0], af[2][1], af[3][1], b0, b1v);
                }
            }
        }
    }
    __syncthreads();
#pragma unroll
    for (int mt = 0; mt < 2; mt++)
#pragma unroll
        for (int nt = 0; nt < 8; nt++) {
            int tok0 = wm * 32 + mt * 16 + qr;
            int o0 = wn * 64 + nt * 8 + 2 * qc;
            float4 c = acc2[mt][nt];
            Cst[o0 * 130 + tok0] = c.x;
            Cst[(o0 + 1) * 130 + tok0] = c.y;
            Cst[o0 * 130 + tok0 + 8] = c.z;
            Cst[(o0 + 1) * 130 + tok0 + 8] = c.w;
        }
    __syncthreads();
    int tl = t & 127, og = t >> 7;
    float g0 = G[tl], g1 = G[128 + tl], g2 = G[256 + tl], g3 = G[384 + tl];
    for (int j = 0; j < 64; j++) {
        int o = og * 64 + j;
        float delta = Cst[o * 130 + tl] +
                      g0 * b2[o] + g1 * b2[128 + o] + g2 * b2[256 + o] + g3 * b2[384 + o];
        size_t gi = (o < 64) ? ((size_t)(bt * 64 + o)) * 4096 + hw0 + tl
                             : IMOFF + ((size_t)(bt * 64 + o - 64)) * 4096 + hw0 + tl;
        out[gi] += delta;
    }
}

extern "C" void kernel_launch(void* const* d_in, const int* in_sizes, int n_in,
                              void* d_out, int out_size) {
    const float* x_real = (const float*)d_in[0];
    const float* x_imag = (const float*)d_in[1];
    const float* dt     = (const float*)d_in[2];
    const float* nz_r   = (const float*)d_in[3];
    const float* nz_i   = (const float*)d_in[4];
    const float* ln_s_w = (const float*)d_in[5];
    const float* ln_s_b = (const float*)d_in[6];
    const float* conv_w = (const float*)d_in[7];
    const float* conv_b = (const float*)d_in[8];
    const float* ln_t_w = (const float*)d_in[9];
    const float* ln_t_b = (const float*)d_in[10];
    const float* lam_re = (const float*)d_in[11];
    const float* lam_im = (const float*)d_in[12];
    const float* sb_re  = (const float*)d_in[13];
    const float* sb_im  = (const float*)d_in[14];
    const float* enc_re = (const float*)d_in[15];
    const float* enc_im = (const float*)d_in[16];
    const float* dec_re = (const float*)d_in[17];
    const float* dec_im = (const float*)d_in[18];
    const float* rw     = (const float*)d_in[19];
    const float* rb     = (const float*)d_in[20];
    const float* w1     = (const float*)d_in[21];
    const float* b1     = (const float*)d_in[22];
    const float* w2     = (const float*)d_in[23];
    const float* b2     = (const float*)d_in[24];
    float* out = (float*)d_out;

    // conv smem: max(A 264*36 + B 32*136, C 128*130) words
    int conv_smem = 128 * 130 * 4;  // 66560 B (A+B = 55424 B)
    int moe_smem = (2 * 128 * MOE_ASTR + 32 * MOE_BSTR + 512) * 4;  // 154624 B
    cudaFuncSetAttribute(k_conv, cudaFuncAttributeMaxDynamicSharedMemorySize, conv_smem);
    cudaFuncSetAttribute(k_moe, cudaFuncAttributeMaxDynamicSharedMemorySize, moe_smem);

    k_setup<<<8, 256>>>(dt, lam_re, lam_im);
    k_sln<<<2048, 256>>>(x_real, x_imag, ln_s_w, ln_s_b);
    k_conv<<<dim3(32, 32), 256, conv_smem>>>(conv_w, conv_b, x_real, x_imag);
    k_enc<<<2048, 256>>>(ln_t_w, ln_t_b, enc_re, enc_im, sb_re, sb_im, nz_r, nz_i);
    k_scan<<<2048, 256>>>();
    k_dec<<<2048, 256>>>(dec_re, dec_im, out);
    k_moe<<<1024, 256, moe_smem>>>(rw, rb, w1, b1, w2, b2, out);
}